// round 2
// baseline (speedup 1.0000x reference)
#include <cuda_runtime.h>

#define D_MODEL 1024
#define N_HEADS 16
#define D_KH    64
#define B_      4
#define S_      2048
#define M_TOT   (B_ * S_)   // 8192

// Scratch (allocation-free rule: __device__ globals)
__device__ float g_q[M_TOT * D_MODEL];     // [B,H,S,64]
__device__ float g_k[M_TOT * D_MODEL];     // [B,H,S,64]
__device__ float g_v[M_TOT * D_MODEL];     // [B,H,S,64]
__device__ float g_attn[M_TOT * D_MODEL];  // [B,S,D]

// ---------------------------------------------------------------------------
// C[M,N] = X[M,K] @ W[N,K]^T + bias  (GEMM_NT, M=8192, N=K=1024)
// BM=BN=128, BK=8, 256 threads, 8x8 micro-tile.
// HEAD_SPLIT=1: write C[m][n] to [B,H,S,64] layout (n -> (h,dk), m -> (b,s))
// ---------------------------------------------------------------------------
template <int HEAD_SPLIT>
__global__ void __launch_bounds__(256, 2)
proj_gemm(const float* __restrict__ X, const float* __restrict__ W,
          const float* __restrict__ bias, float* __restrict__ out)
{
    __shared__ float As[8][128];
    __shared__ float Bs[8][128];

    const int tid = threadIdx.x;
    const int tx  = tid & 15;
    const int ty  = tid >> 4;
    const int m0  = blockIdx.y * 128;
    const int n0  = blockIdx.x * 128;

    const int lrow = tid >> 1;        // 0..127
    const int lc   = (tid & 1) * 4;   // 0 or 4
    const float* Ap = X + (size_t)(m0 + lrow) * D_MODEL + lc;
    const float* Bp = W + (size_t)(n0 + lrow) * D_MODEL + lc;

    float acc[8][8];
#pragma unroll
    for (int i = 0; i < 8; i++)
#pragma unroll
        for (int j = 0; j < 8; j++) acc[i][j] = 0.f;

    for (int k0 = 0; k0 < D_MODEL; k0 += 8) {
        float4 a  = *(const float4*)(Ap + k0);
        float4 bq = *(const float4*)(Bp + k0);
        __syncthreads();
        As[lc + 0][lrow] = a.x;  As[lc + 1][lrow] = a.y;
        As[lc + 2][lrow] = a.z;  As[lc + 3][lrow] = a.w;
        Bs[lc + 0][lrow] = bq.x; Bs[lc + 1][lrow] = bq.y;
        Bs[lc + 2][lrow] = bq.z; Bs[lc + 3][lrow] = bq.w;
        __syncthreads();
#pragma unroll
        for (int kk = 0; kk < 8; kk++) {
            float af[8], bf[8];
            *(float4*)(af)     = *(const float4*)&As[kk][ty * 4];
            *(float4*)(af + 4) = *(const float4*)&As[kk][64 + ty * 4];
            *(float4*)(bf)     = *(const float4*)&Bs[kk][tx * 4];
            *(float4*)(bf + 4) = *(const float4*)&Bs[kk][64 + tx * 4];
#pragma unroll
            for (int i = 0; i < 8; i++)
#pragma unroll
                for (int j = 0; j < 8; j++) acc[i][j] += af[i] * bf[j];
        }
    }

#pragma unroll
    for (int i = 0; i < 8; i++) {
        const int m = m0 + ((i < 4) ? (ty * 4 + i) : (64 + ty * 4 + i - 4));
#pragma unroll
        for (int j = 0; j < 8; j++) {
            const int n = n0 + ((j < 4) ? (tx * 4 + j) : (64 + tx * 4 + j - 4));
            const float c = acc[i][j] + bias[n];
            if (HEAD_SPLIT) {
                const int b = m >> 11, s = m & (S_ - 1);
                const int h = n >> 6,  dk = n & 63;
                out[(((size_t)(b * N_HEADS + h) * S_) + s) * D_KH + dk] = c;
            } else {
                out[(size_t)m * D_MODEL + n] = c;
            }
        }
    }
}

// ---------------------------------------------------------------------------
// Causal flash attention. One block per (q-tile of 64, head, batch).
// 256 threads = 16x16; each thread owns a 4(q) x 4(j) score micro-tile and
// a 4(q) x 4(d) output micro-tile. Online softmax with width-16 shuffles.
// ---------------------------------------------------------------------------
__global__ void __launch_bounds__(256)
attn_kernel(const float* __restrict__ gq, const float* __restrict__ gk,
            const float* __restrict__ gv, float* __restrict__ gout)
{
    extern __shared__ float sm[];
    float* Qs = sm;                 // [64][68]  (scaled by 1/8)
    float* Vs = sm + 64 * 68;       // [64][68]  V[j][d]
    float* Ks = sm + 2 * 64 * 68;   // [64][68]  transposed: K[d][j]
    float* Ps = sm + 3 * 64 * 68;   // [64][65]  probs

    const int qt = blockIdx.x, h = blockIdx.y, b = blockIdx.z;
    const int tid = threadIdx.x;
    const int tx = tid & 15, ty = tid >> 4;

    const size_t head_off = (size_t)(b * N_HEADS + h) * S_ * D_KH;
    const float* Qb = gq + head_off + (size_t)qt * 64 * D_KH;
    const float* Kb = gk + head_off;
    const float* Vb = gv + head_off;

    const int lr = tid >> 2;   // 0..63
    const int lq = tid & 3;    // 0..3

    // Load Q tile (pre-scaled by 1/sqrt(Dk) = 0.125)
#pragma unroll
    for (int r = 0; r < 4; r++) {
        const int d = (lq + 4 * r) * 4;
        float4 q = *(const float4*)(Qb + lr * D_KH + d);
        q.x *= 0.125f; q.y *= 0.125f; q.z *= 0.125f; q.w *= 0.125f;
        *(float4*)&Qs[lr * 68 + d] = q;
    }

    float m_i[4], l_i[4], o[4][4];
#pragma unroll
    for (int i = 0; i < 4; i++) {
        m_i[i] = -1e30f; l_i[i] = 0.f;
#pragma unroll
        for (int j = 0; j < 4; j++) o[i][j] = 0.f;
    }

    const unsigned FULL = 0xffffffffu;

    for (int kt = 0; kt <= qt; kt++) {
        __syncthreads();
        // Load K (transposed) and V tiles
#pragma unroll
        for (int r = 0; r < 4; r++) {
            const int d = (lq + 4 * r) * 4;
            const float4 kv = *(const float4*)(Kb + (size_t)(kt * 64 + lr) * D_KH + d);
            Ks[(d + 0) * 68 + lr] = kv.x;
            Ks[(d + 1) * 68 + lr] = kv.y;
            Ks[(d + 2) * 68 + lr] = kv.z;
            Ks[(d + 3) * 68 + lr] = kv.w;
            const float4 vv = *(const float4*)(Vb + (size_t)(kt * 64 + lr) * D_KH + d);
            *(float4*)&Vs[lr * 68 + d] = vv;
        }
        __syncthreads();

        // S = Q K^T (scaled)
        float s[4][4];
#pragma unroll
        for (int i = 0; i < 4; i++)
#pragma unroll
            for (int j = 0; j < 4; j++) s[i][j] = 0.f;

#pragma unroll 16
        for (int d = 0; d < 64; d++) {
            const float4 kf = *(const float4*)&Ks[d * 68 + tx * 4];
            float qf[4];
#pragma unroll
            for (int i = 0; i < 4; i++) qf[i] = Qs[(ty * 4 + i) * 68 + d];
#pragma unroll
            for (int i = 0; i < 4; i++) {
                s[i][0] += qf[i] * kf.x;
                s[i][1] += qf[i] * kf.y;
                s[i][2] += qf[i] * kf.z;
                s[i][3] += qf[i] * kf.w;
            }
        }

        // Online softmax per q-row (4 rows per thread, reduce across 16 lanes)
#pragma unroll
        for (int i = 0; i < 4; i++) {
            if (kt == qt) {
                const int qg = ty * 4 + i;
#pragma unroll
                for (int jj = 0; jj < 4; jj++)
                    if (tx * 4 + jj > qg) s[i][jj] = -1e30f;
            }
            float mx = fmaxf(fmaxf(s[i][0], s[i][1]), fmaxf(s[i][2], s[i][3]));
            mx = fmaxf(mx, __shfl_xor_sync(FULL, mx, 1, 16));
            mx = fmaxf(mx, __shfl_xor_sync(FULL, mx, 2, 16));
            mx = fmaxf(mx, __shfl_xor_sync(FULL, mx, 4, 16));
            mx = fmaxf(mx, __shfl_xor_sync(FULL, mx, 8, 16));
            const float mnew  = fmaxf(m_i[i], mx);
            const float alpha = __expf(m_i[i] - mnew);
            float rs = 0.f;
#pragma unroll
            for (int jj = 0; jj < 4; jj++) {
                const float p = __expf(s[i][jj] - mnew);
                Ps[(ty * 4 + i) * 65 + tx * 4 + jj] = p;
                rs += p;
            }
            rs += __shfl_xor_sync(FULL, rs, 1, 16);
            rs += __shfl_xor_sync(FULL, rs, 2, 16);
            rs += __shfl_xor_sync(FULL, rs, 4, 16);
            rs += __shfl_xor_sync(FULL, rs, 8, 16);
            l_i[i] = l_i[i] * alpha + rs;
            m_i[i] = mnew;
#pragma unroll
            for (int jj = 0; jj < 4; jj++) o[i][jj] *= alpha;
        }
        __syncwarp();   // Ps rows for this thread are written by its own warp

        // O += P V
#pragma unroll 8
        for (int j = 0; j < 64; j++) {
            const float4 vf = *(const float4*)&Vs[j * 68 + tx * 4];
            float pf[4];
#pragma unroll
            for (int i = 0; i < 4; i++) pf[i] = Ps[(ty * 4 + i) * 65 + j];
#pragma unroll
            for (int i = 0; i < 4; i++) {
                o[i][0] += pf[i] * vf.x;
                o[i][1] += pf[i] * vf.y;
                o[i][2] += pf[i] * vf.z;
                o[i][3] += pf[i] * vf.w;
            }
        }
    }

    // Epilogue: write [B,S,D] layout
    float* op = gout + ((size_t)(b * S_ + qt * 64)) * D_MODEL + h * D_KH;
#pragma unroll
    for (int i = 0; i < 4; i++) {
        const float inv = 1.0f / l_i[i];
        float4 r;
        r.x = o[i][0] * inv; r.y = o[i][1] * inv;
        r.z = o[i][2] * inv; r.w = o[i][3] * inv;
        *(float4*)(op + (size_t)(ty * 4 + i) * D_MODEL + tx * 4) = r;
    }
}

// ---------------------------------------------------------------------------
extern "C" void kernel_launch(void* const* d_in, const int* in_sizes, int n_in,
                              void* d_out, int out_size)
{
    const float* Q   = (const float*)d_in[0];
    const float* K   = (const float*)d_in[1];
    const float* V   = (const float*)d_in[2];
    // d_in[3] = causal mask (int32) — causality is hardcoded
    const float* W_q = (const float*)d_in[4];
    const float* b_q = (const float*)d_in[5];
    const float* W_k = (const float*)d_in[6];
    const float* b_k = (const float*)d_in[7];
    const float* W_v = (const float*)d_in[8];
    const float* b_v = (const float*)d_in[9];
    const float* W_o = (const float*)d_in[10];
    const float* b_o = (const float*)d_in[11];
    float* out = (float*)d_out;

    float *gq, *gk, *gv, *gattn;
    cudaGetSymbolAddress((void**)&gq, g_q);
    cudaGetSymbolAddress((void**)&gk, g_k);
    cudaGetSymbolAddress((void**)&gv, g_v);
    cudaGetSymbolAddress((void**)&gattn, g_attn);

    dim3 gproj(D_MODEL / 128, M_TOT / 128);  // (8, 64)
    dim3 tb(256);

    proj_gemm<1><<<gproj, tb>>>(Q, W_q, b_q, gq);
    proj_gemm<1><<<gproj, tb>>>(K, W_k, b_k, gk);
    proj_gemm<1><<<gproj, tb>>>(V, W_v, b_v, gv);

    const int smem = (3 * 64 * 68 + 64 * 65) * (int)sizeof(float);  // 68,864 B
    cudaFuncSetAttribute(attn_kernel, cudaFuncAttributeMaxDynamicSharedMemorySize, smem);
    attn_kernel<<<dim3(S_ / 64, N_HEADS, B_), tb, smem>>>(gq, gk, gv, gattn);

    proj_gemm<0><<<gproj, tb>>>(gattn, W_o, b_o, out);
}

// round 4
// speedup vs baseline: 2.5486x; 2.5486x over previous
#include <cuda_runtime.h>
#include <cstdint>

#define D_MODEL 1024
#define N_HEADS 16
#define D_KH    64
#define B_      4
#define S_      2048
#define M_TOT   (B_ * S_)   // 8192

// ---------------- scratch (__device__ globals: allocation-free rule) -------
__device__ float g_q[M_TOT * D_MODEL];      // [B,H,S,64]
__device__ float g_k[M_TOT * D_MODEL];
__device__ float g_v[M_TOT * D_MODEL];
__device__ float g_attn[M_TOT * D_MODEL];   // [B,S,D]

// ---------------- helpers ---------------------------------------------------
__device__ __forceinline__ float to_tf32(float x) {
    uint32_t u;
    asm("cvt.rna.tf32.f32 %0, %1;" : "=r"(u) : "f"(x));
    return __uint_as_float(u);
}
__device__ __forceinline__ void mma8(float* c, const uint32_t* a, const uint32_t* b) {
    asm volatile(
        "mma.sync.aligned.m16n8k8.row.col.f32.tf32.tf32.f32 "
        "{%0,%1,%2,%3}, {%4,%5,%6,%7}, {%8,%9}, {%0,%1,%2,%3};"
        : "+f"(c[0]), "+f"(c[1]), "+f"(c[2]), "+f"(c[3])
        : "r"(a[0]), "r"(a[1]), "r"(a[2]), "r"(a[3]), "r"(b[0]), "r"(b[1]));
}

// ---------------- tf32 mma.sync GEMM ----------------------------------------
// C[M,N] = X[M,K] @ W[N,K]^T + bias.  BM=BN=128, BK=32, 256 thr = 8 warps
// (4M x 2N), warp tile 32x64 (2x8 m16n8k8 atoms / k-step). Double-buffered
// smem with inline f32->tf32(RNA) conversion during staging.
#define BK  32
#define SA  36                    // smem row stride (floats); conflict-free frags
#define STG (128 * SA)            // floats per stage per operand
#define CHUNKS (D_MODEL / BK)     // 32
#define GEMM_SMEM (4 * STG * 4)   // bytes: 2 ops x 2 stages

template <int HEAD_SPLIT>
__global__ void __launch_bounds__(256)
gemm_mma(const float* __restrict__ X, const float* __restrict__ W,
         const float* __restrict__ bias, float* __restrict__ out)
{
    extern __shared__ float smx[];
    float* As = smx;              // [2][128][SA]
    float* Bs = smx + 2 * STG;    // [2][128][SA]

    const int t    = threadIdx.x;
    const int wid  = t >> 5;
    const int lane = t & 31;
    const int g    = lane >> 2;      // group id (0..7)
    const int tig  = lane & 3;       // thread in group
    const int wm   = (wid >> 1) * 32;
    const int wn   = (wid & 1) * 64;
    const int m0   = blockIdx.y * 128;
    const int n0   = blockIdx.x * 128;

    const int srow = t >> 1;            // staging row (0..127)
    const int scol = (t & 1) * 16;      // staging col base
    const float* Xp = X + (size_t)(m0 + srow) * D_MODEL + scol;
    const float* Wp = W + (size_t)(n0 + srow) * D_MODEL + scol;

    float4 ra[4], rb[4];
    float acc[2][8][4];
#pragma unroll
    for (int i = 0; i < 2; i++)
#pragma unroll
        for (int j = 0; j < 8; j++)
#pragma unroll
            for (int q = 0; q < 4; q++) acc[i][j][q] = 0.f;

#define LDREG(c) {                                                     \
        const int k0 = (c) * BK;                                       \
        _Pragma("unroll")                                              \
        for (int q = 0; q < 4; q++) {                                  \
            ra[q] = *(const float4*)(Xp + k0 + 4 * q);                 \
            rb[q] = *(const float4*)(Wp + k0 + 4 * q);                 \
        }                                                              \
    }
#define STSMEM(s) {                                                    \
        float* ap = As + (s) * STG + srow * SA + scol;                 \
        float* bp = Bs + (s) * STG + srow * SA + scol;                 \
        _Pragma("unroll")                                              \
        for (int q = 0; q < 4; q++) {                                  \
            float4 va = ra[q], vb = rb[q];                             \
            va.x = to_tf32(va.x); va.y = to_tf32(va.y);                \
            va.z = to_tf32(va.z); va.w = to_tf32(va.w);                \
            vb.x = to_tf32(vb.x); vb.y = to_tf32(vb.y);                \
            vb.z = to_tf32(vb.z); vb.w = to_tf32(vb.w);                \
            *(float4*)(ap + 4 * q) = va;                               \
            *(float4*)(bp + 4 * q) = vb;                               \
        }                                                              \
    }

    LDREG(0);
    STSMEM(0);
    __syncthreads();

    for (int c = 0; c < CHUNKS; c++) {
        const int s = c & 1;
        if (c + 1 < CHUNKS) LDREG(c + 1);

        const float* Af = As + s * STG;
        const float* Bf = Bs + s * STG;
#pragma unroll
        for (int ks = 0; ks < 4; ks++) {
            const int k = ks * 8;
            uint32_t afr[2][4];
#pragma unroll
            for (int i = 0; i < 2; i++) {
                const float* ap = Af + (wm + i * 16 + g) * SA + k + tig;
                afr[i][0] = __float_as_uint(ap[0]);
                afr[i][1] = __float_as_uint(ap[8 * SA]);
                afr[i][2] = __float_as_uint(ap[4]);
                afr[i][3] = __float_as_uint(ap[8 * SA + 4]);
            }
#pragma unroll
            for (int j = 0; j < 8; j++) {
                const float* bp = Bf + (wn + j * 8 + g) * SA + k + tig;
                uint32_t bfr[2] = { __float_as_uint(bp[0]), __float_as_uint(bp[4]) };
                mma8(acc[0][j], afr[0], bfr);
                mma8(acc[1][j], afr[1], bfr);
            }
        }

        if (c + 1 < CHUNKS) {
            __syncthreads();
            STSMEM((c + 1) & 1);
            __syncthreads();
        }
    }

    // ---- epilogue: bias add + (optional) head-split store ----
#pragma unroll
    for (int i = 0; i < 2; i++) {
        const int r0 = m0 + wm + i * 16 + g;
#pragma unroll
        for (int j = 0; j < 8; j++) {
            const int n = n0 + wn + j * 8 + tig * 2;
            const float bx = bias[n], by = bias[n + 1];
            float2 lo = { acc[i][j][0] + bx, acc[i][j][1] + by };
            float2 hi = { acc[i][j][2] + bx, acc[i][j][3] + by };
            if (HEAD_SPLIT) {
                const int h = n >> 6, dk = n & 63;
                const int b0r = r0 >> 11, s0r = r0 & (S_ - 1);
                float* d0 = out + (((size_t)(b0r * N_HEADS + h) * S_) + s0r) * D_KH + dk;
                *(float2*)d0 = lo;
                const int r1 = r0 + 8;
                const int b1r = r1 >> 11, s1r = r1 & (S_ - 1);
                float* d1 = out + (((size_t)(b1r * N_HEADS + h) * S_) + s1r) * D_KH + dk;
                *(float2*)d1 = hi;
            } else {
                *(float2*)(out + (size_t)r0 * D_MODEL + n) = lo;
                *(float2*)(out + (size_t)(r0 + 8) * D_MODEL + n) = hi;
            }
        }
    }
}

// ---------------- causal flash attention (unchanged baseline) ---------------
__global__ void __launch_bounds__(256)
attn_kernel(const float* __restrict__ gq, const float* __restrict__ gk,
            const float* __restrict__ gv, float* __restrict__ gout)
{
    extern __shared__ float sm[];
    float* Qs = sm;
    float* Vs = sm + 64 * 68;
    float* Ks = sm + 2 * 64 * 68;
    float* Ps = sm + 3 * 64 * 68;

    const int qt = blockIdx.x, h = blockIdx.y, b = blockIdx.z;
    const int tid = threadIdx.x;
    const int tx = tid & 15, ty = tid >> 4;

    const size_t head_off = (size_t)(b * N_HEADS + h) * S_ * D_KH;
    const float* Qb = gq + head_off + (size_t)qt * 64 * D_KH;
    const float* Kb = gk + head_off;
    const float* Vb = gv + head_off;

    const int lr = tid >> 2;
    const int lq = tid & 3;

#pragma unroll
    for (int r = 0; r < 4; r++) {
        const int d = (lq + 4 * r) * 4;
        float4 q = *(const float4*)(Qb + lr * D_KH + d);
        q.x *= 0.125f; q.y *= 0.125f; q.z *= 0.125f; q.w *= 0.125f;
        *(float4*)&Qs[lr * 68 + d] = q;
    }

    float m_i[4], l_i[4], o[4][4];
#pragma unroll
    for (int i = 0; i < 4; i++) {
        m_i[i] = -1e30f; l_i[i] = 0.f;
#pragma unroll
        for (int j = 0; j < 4; j++) o[i][j] = 0.f;
    }

    const unsigned FULL = 0xffffffffu;

    for (int kt = 0; kt <= qt; kt++) {
        __syncthreads();
#pragma unroll
        for (int r = 0; r < 4; r++) {
            const int d = (lq + 4 * r) * 4;
            const float4 kv = *(const float4*)(Kb + (size_t)(kt * 64 + lr) * D_KH + d);
            Ks[(d + 0) * 68 + lr] = kv.x;
            Ks[(d + 1) * 68 + lr] = kv.y;
            Ks[(d + 2) * 68 + lr] = kv.z;
            Ks[(d + 3) * 68 + lr] = kv.w;
            const float4 vv = *(const float4*)(Vb + (size_t)(kt * 64 + lr) * D_KH + d);
            *(float4*)&Vs[lr * 68 + d] = vv;
        }
        __syncthreads();

        float s[4][4];
#pragma unroll
        for (int i = 0; i < 4; i++)
#pragma unroll
            for (int j = 0; j < 4; j++) s[i][j] = 0.f;

#pragma unroll 16
        for (int d = 0; d < 64; d++) {
            const float4 kf = *(const float4*)&Ks[d * 68 + tx * 4];
            float qf[4];
#pragma unroll
            for (int i = 0; i < 4; i++) qf[i] = Qs[(ty * 4 + i) * 68 + d];
#pragma unroll
            for (int i = 0; i < 4; i++) {
                s[i][0] += qf[i] * kf.x;
                s[i][1] += qf[i] * kf.y;
                s[i][2] += qf[i] * kf.z;
                s[i][3] += qf[i] * kf.w;
            }
        }

#pragma unroll
        for (int i = 0; i < 4; i++) {
            if (kt == qt) {
                const int qg = ty * 4 + i;
#pragma unroll
                for (int jj = 0; jj < 4; jj++)
                    if (tx * 4 + jj > qg) s[i][jj] = -1e30f;
            }
            float mx = fmaxf(fmaxf(s[i][0], s[i][1]), fmaxf(s[i][2], s[i][3]));
            mx = fmaxf(mx, __shfl_xor_sync(FULL, mx, 1, 16));
            mx = fmaxf(mx, __shfl_xor_sync(FULL, mx, 2, 16));
            mx = fmaxf(mx, __shfl_xor_sync(FULL, mx, 4, 16));
            mx = fmaxf(mx, __shfl_xor_sync(FULL, mx, 8, 16));
            const float mnew  = fmaxf(m_i[i], mx);
            const float alpha = __expf(m_i[i] - mnew);
            float rs = 0.f;
#pragma unroll
            for (int jj = 0; jj < 4; jj++) {
                const float p = __expf(s[i][jj] - mnew);
                Ps[(ty * 4 + i) * 65 + tx * 4 + jj] = p;
                rs += p;
            }
            rs += __shfl_xor_sync(FULL, rs, 1, 16);
            rs += __shfl_xor_sync(FULL, rs, 2, 16);
            rs += __shfl_xor_sync(FULL, rs, 4, 16);
            rs += __shfl_xor_sync(FULL, rs, 8, 16);
            l_i[i] = l_i[i] * alpha + rs;
            m_i[i] = mnew;
#pragma unroll
            for (int jj = 0; jj < 4; jj++) o[i][jj] *= alpha;
        }
        __syncwarp();

#pragma unroll 8
        for (int j = 0; j < 64; j++) {
            const float4 vf = *(const float4*)&Vs[j * 68 + tx * 4];
            float pf[4];
#pragma unroll
            for (int i = 0; i < 4; i++) pf[i] = Ps[(ty * 4 + i) * 65 + j];
#pragma unroll
            for (int i = 0; i < 4; i++) {
                o[i][0] += pf[i] * vf.x;
                o[i][1] += pf[i] * vf.y;
                o[i][2] += pf[i] * vf.z;
                o[i][3] += pf[i] * vf.w;
            }
        }
    }

    float* op = gout + ((size_t)(b * S_ + qt * 64)) * D_MODEL + h * D_KH;
#pragma unroll
    for (int i = 0; i < 4; i++) {
        const float inv = 1.0f / l_i[i];
        float4 r;
        r.x = o[i][0] * inv; r.y = o[i][1] * inv;
        r.z = o[i][2] * inv; r.w = o[i][3] * inv;
        *(float4*)(op + (size_t)(ty * 4 + i) * D_MODEL + tx * 4) = r;
    }
}

// ---------------- host ------------------------------------------------------
extern "C" void kernel_launch(void* const* d_in, const int* in_sizes, int n_in,
                              void* d_out, int out_size)
{
    const float* Q   = (const float*)d_in[0];
    const float* K   = (const float*)d_in[1];
    const float* V   = (const float*)d_in[2];
    const float* W_q = (const float*)d_in[4];
    const float* b_q = (const float*)d_in[5];
    const float* W_k = (const float*)d_in[6];
    const float* b_k = (const float*)d_in[7];
    const float* W_v = (const float*)d_in[8];
    const float* b_v = (const float*)d_in[9];
    const float* W_o = (const float*)d_in[10];
    const float* b_o = (const float*)d_in[11];
    float* out = (float*)d_out;

    float *gq, *gk, *gv, *gattn;
    cudaGetSymbolAddress((void**)&gq, g_q);
    cudaGetSymbolAddress((void**)&gk, g_k);
    cudaGetSymbolAddress((void**)&gv, g_v);
    cudaGetSymbolAddress((void**)&gattn, g_attn);

    cudaFuncSetAttribute(gemm_mma<0>, cudaFuncAttributeMaxDynamicSharedMemorySize, GEMM_SMEM);
    cudaFuncSetAttribute(gemm_mma<1>, cudaFuncAttributeMaxDynamicSharedMemorySize, GEMM_SMEM);

    dim3 ggrid(D_MODEL / 128, M_TOT / 128);   // (8, 64)
    gemm_mma<1><<<ggrid, 256, GEMM_SMEM>>>(Q, W_q, b_q, gq);
    gemm_mma<1><<<ggrid, 256, GEMM_SMEM>>>(K, W_k, b_k, gk);
    gemm_mma<1><<<ggrid, 256, GEMM_SMEM>>>(V, W_v, b_v, gv);

    const int asmem = (3 * 64 * 68 + 64 * 65) * (int)sizeof(float);
    cudaFuncSetAttribute(attn_kernel, cudaFuncAttributeMaxDynamicSharedMemorySize, asmem);
    attn_kernel<<<dim3(S_ / 64, N_HEADS, B_), 256, asmem>>>(gq, gk, gv, gattn);

    gemm_mma<0><<<ggrid, 256, GEMM_SMEM>>>(gattn, W_o, b_o, out);
}

// round 6
// speedup vs baseline: 3.3853x; 1.3283x over previous
#include <cuda_runtime.h>
#include <cstdint>

#define D_MODEL 1024
#define N_HEADS 16
#define D_KH    64
#define B_      4
#define S_      2048
#define M_TOT   (B_ * S_)   // 8192

// ---------------- scratch (__device__ globals: allocation-free rule) -------
__device__ float g_q[M_TOT * D_MODEL];      // [B,H,S,64]
__device__ float g_k[M_TOT * D_MODEL];
__device__ float g_v[M_TOT * D_MODEL];
__device__ float g_attn[M_TOT * D_MODEL];   // [B,S,D]

// ---------------- helpers ---------------------------------------------------
__device__ __forceinline__ float to_tf32(float x) {
    uint32_t u;
    asm("cvt.rna.tf32.f32 %0, %1;" : "=r"(u) : "f"(x));
    return __uint_as_float(u);
}
__device__ __forceinline__ void mma8(float* c, const uint32_t* a, const uint32_t* b) {
    asm volatile(
        "mma.sync.aligned.m16n8k8.row.col.f32.tf32.tf32.f32 "
        "{%0,%1,%2,%3}, {%4,%5,%6,%7}, {%8,%9}, {%0,%1,%2,%3};"
        : "+f"(c[0]), "+f"(c[1]), "+f"(c[2]), "+f"(c[3])
        : "r"(a[0]), "r"(a[1]), "r"(a[2]), "r"(a[3]), "r"(b[0]), "r"(b[1]));
}

// ---------------- tf32 mma.sync GEMM (unchanged from R4) --------------------
#define BK  32
#define SA  36
#define STG (128 * SA)
#define CHUNKS (D_MODEL / BK)
#define GEMM_SMEM (4 * STG * 4)

template <int HEAD_SPLIT>
__global__ void __launch_bounds__(256)
gemm_mma(const float* __restrict__ X, const float* __restrict__ W,
         const float* __restrict__ bias, float* __restrict__ out)
{
    extern __shared__ float smx[];
    float* As = smx;
    float* Bs = smx + 2 * STG;

    const int t    = threadIdx.x;
    const int wid  = t >> 5;
    const int lane = t & 31;
    const int g    = lane >> 2;
    const int tig  = lane & 3;
    const int wm   = (wid >> 1) * 32;
    const int wn   = (wid & 1) * 64;
    const int m0   = blockIdx.y * 128;
    const int n0   = blockIdx.x * 128;

    const int srow = t >> 1;
    const int scol = (t & 1) * 16;
    const float* Xp = X + (size_t)(m0 + srow) * D_MODEL + scol;
    const float* Wp = W + (size_t)(n0 + srow) * D_MODEL + scol;

    float4 ra[4], rb[4];
    float acc[2][8][4];
#pragma unroll
    for (int i = 0; i < 2; i++)
#pragma unroll
        for (int j = 0; j < 8; j++)
#pragma unroll
            for (int q = 0; q < 4; q++) acc[i][j][q] = 0.f;

#define LDREG(c) {                                                     \
        const int k0 = (c) * BK;                                       \
        _Pragma("unroll")                                              \
        for (int q = 0; q < 4; q++) {                                  \
            ra[q] = *(const float4*)(Xp + k0 + 4 * q);                 \
            rb[q] = *(const float4*)(Wp + k0 + 4 * q);                 \
        }                                                              \
    }
#define STSMEM(s) {                                                    \
        float* ap = As + (s) * STG + srow * SA + scol;                 \
        float* bp = Bs + (s) * STG + srow * SA + scol;                 \
        _Pragma("unroll")                                              \
        for (int q = 0; q < 4; q++) {                                  \
            float4 va = ra[q], vb = rb[q];                             \
            va.x = to_tf32(va.x); va.y = to_tf32(va.y);                \
            va.z = to_tf32(va.z); va.w = to_tf32(va.w);                \
            vb.x = to_tf32(vb.x); vb.y = to_tf32(vb.y);                \
            vb.z = to_tf32(vb.z); vb.w = to_tf32(vb.w);                \
            *(float4*)(ap + 4 * q) = va;                               \
            *(float4*)(bp + 4 * q) = vb;                               \
        }                                                              \
    }

    LDREG(0);
    STSMEM(0);
    __syncthreads();

    for (int c = 0; c < CHUNKS; c++) {
        const int s = c & 1;
        if (c + 1 < CHUNKS) LDREG(c + 1);

        const float* Af = As + s * STG;
        const float* Bf = Bs + s * STG;
#pragma unroll
        for (int ks = 0; ks < 4; ks++) {
            const int k = ks * 8;
            uint32_t afr[2][4];
#pragma unroll
            for (int i = 0; i < 2; i++) {
                const float* ap = Af + (wm + i * 16 + g) * SA + k + tig;
                afr[i][0] = __float_as_uint(ap[0]);
                afr[i][1] = __float_as_uint(ap[8 * SA]);
                afr[i][2] = __float_as_uint(ap[4]);
                afr[i][3] = __float_as_uint(ap[8 * SA + 4]);
            }
#pragma unroll
            for (int j = 0; j < 8; j++) {
                const float* bp = Bf + (wn + j * 8 + g) * SA + k + tig;
                uint32_t bfr[2] = { __float_as_uint(bp[0]), __float_as_uint(bp[4]) };
                mma8(acc[0][j], afr[0], bfr);
                mma8(acc[1][j], afr[1], bfr);
            }
        }

        if (c + 1 < CHUNKS) {
            __syncthreads();
            STSMEM((c + 1) & 1);
            __syncthreads();
        }
    }

#pragma unroll
    for (int i = 0; i < 2; i++) {
        const int r0 = m0 + wm + i * 16 + g;
#pragma unroll
        for (int j = 0; j < 8; j++) {
            const int n = n0 + wn + j * 8 + tig * 2;
            const float bx = bias[n], by = bias[n + 1];
            float2 lo = { acc[i][j][0] + bx, acc[i][j][1] + by };
            float2 hi = { acc[i][j][2] + bx, acc[i][j][3] + by };
            if (HEAD_SPLIT) {
                const int h = n >> 6, dk = n & 63;
                const int b0r = r0 >> 11, s0r = r0 & (S_ - 1);
                *(float2*)(out + (((size_t)(b0r * N_HEADS + h) * S_) + s0r) * D_KH + dk) = lo;
                const int r1 = r0 + 8;
                const int b1r = r1 >> 11, s1r = r1 & (S_ - 1);
                *(float2*)(out + (((size_t)(b1r * N_HEADS + h) * S_) + s1r) * D_KH + dk) = hi;
            } else {
                *(float2*)(out + (size_t)r0 * D_MODEL + n) = lo;
                *(float2*)(out + (size_t)(r0 + 8) * D_MODEL + n) = hi;
            }
        }
    }
}

// ---------------- tf32 mma.sync causal flash attention ----------------------
// 64 q-rows per CTA, 128 threads = 4 warps x 16 rows. Q fragments in regs.
// Per k-tile: QK^T (64 HMMA), fragment softmax, P via per-warp smem, PV (64).
// Strides: Ks/Ps 68 (bank 4g+tig, conflict-free), Vs 72 (bank 8tig+g).
#define KST 68
#define VST 72
#define ATTN_SMEM ((64 * KST + 64 * VST + 64 * KST) * 4)   // 53248 B

__global__ void __launch_bounds__(128)
attn_mma(const float* __restrict__ gq, const float* __restrict__ gk,
         const float* __restrict__ gv, float* __restrict__ gout)
{
    extern __shared__ float sm[];
    float* Ks = sm;                          // [64][68]
    float* Vs = sm + 64 * KST;               // [64][72]
    float* Ps = sm + 64 * KST + 64 * VST;    // [64][68] (Q staging, then P)

    const int qt = (S_ / 64 - 1) - blockIdx.x;   // heavy CTAs first
    const int h = blockIdx.y, b = blockIdx.z;
    const int tid  = threadIdx.x;
    const int w    = tid >> 5;
    const int lane = tid & 31;
    const int g    = lane >> 2;
    const int tig  = lane & 3;

    const size_t head = (size_t)(b * N_HEADS + h) * S_ * D_KH;
    const float* Qb = gq + head + (size_t)qt * 64 * D_KH;
    const float* Kb = gk + head;
    const float* Vb = gv + head;

    const int srow = tid >> 1;
    const int scol = (tid & 1) * 32;

    // stage Q (scaled 1/8, tf32) into Ps
    {
        const float* qp = Qb + (size_t)srow * D_KH + scol;
        float* dp = Ps + srow * KST + scol;
#pragma unroll
        for (int q4 = 0; q4 < 8; q4++) {
            float4 v = *(const float4*)(qp + 4 * q4);
            v.x = to_tf32(v.x * 0.125f); v.y = to_tf32(v.y * 0.125f);
            v.z = to_tf32(v.z * 0.125f); v.w = to_tf32(v.w * 0.125f);
            *(float4*)(dp + 4 * q4) = v;
        }
    }
    __syncthreads();

    uint32_t aQ[8][4];
    {
        const float* Qw = Ps + (w * 16) * KST;
#pragma unroll
        for (int ks = 0; ks < 8; ks++) {
            aQ[ks][0] = __float_as_uint(Qw[g * KST + ks * 8 + tig]);
            aQ[ks][1] = __float_as_uint(Qw[(g + 8) * KST + ks * 8 + tig]);
            aQ[ks][2] = __float_as_uint(Qw[g * KST + ks * 8 + tig + 4]);
            aQ[ks][3] = __float_as_uint(Qw[(g + 8) * KST + ks * 8 + tig + 4]);
        }
    }

    float m0 = -1e30f, m1 = -1e30f, l0 = 0.f, l1 = 0.f;
    float of[8][4];
#pragma unroll
    for (int na = 0; na < 8; na++)
#pragma unroll
        for (int q = 0; q < 4; q++) of[na][q] = 0.f;

    const unsigned FULL = 0xffffffffu;
    const int r0loc = w * 16 + g;

    for (int kt = 0; kt <= qt; kt++) {
        __syncthreads();
        {   // stage K (tf32) and V (tf32)
            const float* kp = Kb + (size_t)(kt * 64 + srow) * D_KH + scol;
            const float* vp = Vb + (size_t)(kt * 64 + srow) * D_KH + scol;
            float* kd = Ks + srow * KST + scol;
            float* vd = Vs + srow * VST + scol;
#pragma unroll
            for (int q4 = 0; q4 < 8; q4++) {
                float4 kv = *(const float4*)(kp + 4 * q4);
                kv.x = to_tf32(kv.x); kv.y = to_tf32(kv.y);
                kv.z = to_tf32(kv.z); kv.w = to_tf32(kv.w);
                *(float4*)(kd + 4 * q4) = kv;
                float4 vv = *(const float4*)(vp + 4 * q4);
                vv.x = to_tf32(vv.x); vv.y = to_tf32(vv.y);
                vv.z = to_tf32(vv.z); vv.w = to_tf32(vv.w);
                *(float4*)(vd + 4 * q4) = vv;
            }
        }
        __syncthreads();

        // S = Q K^T
        float sf[8][4];
#pragma unroll
        for (int na = 0; na < 8; na++)
#pragma unroll
            for (int q = 0; q < 4; q++) sf[na][q] = 0.f;
#pragma unroll
        for (int na = 0; na < 8; na++) {
            const float* kp = Ks + (na * 8 + g) * KST + tig;
#pragma unroll
            for (int ks = 0; ks < 8; ks++) {
                uint32_t bb[2] = { __float_as_uint(kp[ks * 8]),
                                   __float_as_uint(kp[ks * 8 + 4]) };
                mma8(sf[na], aQ[ks], bb);
            }
        }

        if (kt == qt) {
#pragma unroll
            for (int na = 0; na < 8; na++) {
                const int c0 = na * 8 + 2 * tig;
                if (c0 > r0loc)     sf[na][0] = -1e30f;
                if (c0 + 1 > r0loc) sf[na][1] = -1e30f;
                if (c0 > r0loc + 8)     sf[na][2] = -1e30f;
                if (c0 + 1 > r0loc + 8) sf[na][3] = -1e30f;
            }
        }

        // fragment online softmax (rows r0loc, r0loc+8)
        float mx0 = -1e30f, mx1 = -1e30f;
#pragma unroll
        for (int na = 0; na < 8; na++) {
            mx0 = fmaxf(mx0, fmaxf(sf[na][0], sf[na][1]));
            mx1 = fmaxf(mx1, fmaxf(sf[na][2], sf[na][3]));
        }
        mx0 = fmaxf(mx0, __shfl_xor_sync(FULL, mx0, 1));
        mx0 = fmaxf(mx0, __shfl_xor_sync(FULL, mx0, 2));
        mx1 = fmaxf(mx1, __shfl_xor_sync(FULL, mx1, 1));
        mx1 = fmaxf(mx1, __shfl_xor_sync(FULL, mx1, 2));
        const float mn0 = fmaxf(m0, mx0), mn1 = fmaxf(m1, mx1);
        const float a0 = __expf(m0 - mn0), a1 = __expf(m1 - mn1);

        float rs0 = 0.f, rs1 = 0.f;
        float* prow0 = Ps + r0loc * KST;
        float* prow1 = prow0 + 8 * KST;
#pragma unroll
        for (int na = 0; na < 8; na++) {
            const float p00 = to_tf32(__expf(sf[na][0] - mn0));
            const float p01 = to_tf32(__expf(sf[na][1] - mn0));
            const float p10 = to_tf32(__expf(sf[na][2] - mn1));
            const float p11 = to_tf32(__expf(sf[na][3] - mn1));
            *(float2*)(prow0 + na * 8 + 2 * tig) = make_float2(p00, p01);
            *(float2*)(prow1 + na * 8 + 2 * tig) = make_float2(p10, p11);
            rs0 += p00 + p01; rs1 += p10 + p11;
            of[na][0] *= a0; of[na][1] *= a0;
            of[na][2] *= a1; of[na][3] *= a1;
        }
        rs0 += __shfl_xor_sync(FULL, rs0, 1);
        rs0 += __shfl_xor_sync(FULL, rs0, 2);
        rs1 += __shfl_xor_sync(FULL, rs1, 1);
        rs1 += __shfl_xor_sync(FULL, rs1, 2);
        l0 = l0 * a0 + rs0; m0 = mn0;
        l1 = l1 * a1 + rs1; m1 = mn1;
        __syncwarp();

        // O += P V
#pragma unroll
        for (int ks = 0; ks < 8; ks++) {
            const float* pr0 = Ps + r0loc * KST + ks * 8 + tig;
            const float* pr1 = pr0 + 8 * KST;
            uint32_t pa[4] = { __float_as_uint(pr0[0]), __float_as_uint(pr1[0]),
                               __float_as_uint(pr0[4]), __float_as_uint(pr1[4]) };
            const float* vp = Vs + (ks * 8 + tig) * VST + g;
#pragma unroll
            for (int na = 0; na < 8; na++) {
                uint32_t bb[2] = { __float_as_uint(vp[na * 8]),
                                   __float_as_uint(vp[na * 8 + 4 * VST]) };
                mma8(of[na], pa, bb);
            }
        }
        __syncwarp();
    }

    // epilogue: write [B,S,D]
    const float i0 = 1.f / l0, i1 = 1.f / l1;
    const int s0 = qt * 64 + r0loc;
    float* o0 = gout + ((size_t)(b * S_) + s0) * D_MODEL + h * D_KH;
    float* o1 = o0 + (size_t)8 * D_MODEL;
#pragma unroll
    for (int na = 0; na < 8; na++) {
        *(float2*)(o0 + na * 8 + 2 * tig) = make_float2(of[na][0] * i0, of[na][1] * i0);
        *(float2*)(o1 + na * 8 + 2 * tig) = make_float2(of[na][2] * i1, of[na][3] * i1);
    }
}

// ---------------- host ------------------------------------------------------
extern "C" void kernel_launch(void* const* d_in, const int* in_sizes, int n_in,
                              void* d_out, int out_size)
{
    const float* Q   = (const float*)d_in[0];
    const float* K   = (const float*)d_in[1];
    const float* V   = (const float*)d_in[2];
    const float* W_q = (const float*)d_in[4];
    const float* b_q = (const float*)d_in[5];
    const float* W_k = (const float*)d_in[6];
    const float* b_k = (const float*)d_in[7];
    const float* W_v = (const float*)d_in[8];
    const float* b_v = (const float*)d_in[9];
    const float* W_o = (const float*)d_in[10];
    const float* b_o = (const float*)d_in[11];
    float* out = (float*)d_out;

    float *gq, *gk, *gv, *gattn;
    cudaGetSymbolAddress((void**)&gq, g_q);
    cudaGetSymbolAddress((void**)&gk, g_k);
    cudaGetSymbolAddress((void**)&gv, g_v);
    cudaGetSymbolAddress((void**)&gattn, g_attn);

    cudaFuncSetAttribute(gemm_mma<0>, cudaFuncAttributeMaxDynamicSharedMemorySize, GEMM_SMEM);
    cudaFuncSetAttribute(gemm_mma<1>, cudaFuncAttributeMaxDynamicSharedMemorySize, GEMM_SMEM);
    cudaFuncSetAttribute(attn_mma, cudaFuncAttributeMaxDynamicSharedMemorySize, ATTN_SMEM);

    dim3 ggrid(D_MODEL / 128, M_TOT / 128);   // (8, 64)
    gemm_mma<1><<<ggrid, 256, GEMM_SMEM>>>(Q, W_q, b_q, gq);
    gemm_mma<1><<<ggrid, 256, GEMM_SMEM>>>(K, W_k, b_k, gk);
    gemm_mma<1><<<ggrid, 256, GEMM_SMEM>>>(V, W_v, b_v, gv);

    attn_mma<<<dim3(S_ / 64, N_HEADS, B_), 128, ATTN_SMEM>>>(gq, gk, gv, gattn);

    gemm_mma<0><<<ggrid, 256, GEMM_SMEM>>>(gattn, W_o, b_o, out);
}

// round 11
// speedup vs baseline: 4.1051x; 1.2126x over previous
#include <cuda_runtime.h>
#include <cstdint>

#define D_MODEL 1024
#define N_HEADS 16
#define D_KH    64
#define B_      4
#define S_      2048
#define M_TOT   (B_ * S_)   // 8192

// ---------------- scratch (__device__ globals: allocation-free rule) -------
__device__ float g_q[M_TOT * D_MODEL];      // [B,H,S,64]
__device__ float g_k[M_TOT * D_MODEL];
__device__ float g_v[M_TOT * D_MODEL];
__device__ float g_attn[M_TOT * D_MODEL];   // [B,S,D]

// ---------------- helpers ---------------------------------------------------
__device__ __forceinline__ float to_tf32(float x) {
    uint32_t u;
    asm("cvt.rna.tf32.f32 %0, %1;" : "=r"(u) : "f"(x));
    return __uint_as_float(u);
}
__device__ __forceinline__ void mma8(float* c, const uint32_t* a, const uint32_t* b) {
    asm volatile(
        "mma.sync.aligned.m16n8k8.row.col.f32.tf32.tf32.f32 "
        "{%0,%1,%2,%3}, {%4,%5,%6,%7}, {%8,%9}, {%0,%1,%2,%3};"
        : "+f"(c[0]), "+f"(c[1]), "+f"(c[2]), "+f"(c[3])
        : "r"(a[0]), "r"(a[1]), "r"(a[2]), "r"(a[3]), "r"(b[0]), "r"(b[1]));
}
__device__ __forceinline__ uint32_t s2u(const void* p) {
    uint32_t r;
    asm("{ .reg .u64 t; cvta.to.shared.u64 t, %1; cvt.u32.u64 %0, t; }" : "=r"(r) : "l"(p));
    return r;
}
__device__ __forceinline__ void cpasync16(uint32_t dst, const void* src) {
    asm volatile("cp.async.cg.shared.global [%0], [%1], 16;" :: "r"(dst), "l"(src));
}
__device__ __forceinline__ void cpcommit() {
    asm volatile("cp.async.commit_group;" ::: "memory");
}
__device__ __forceinline__ void cpwait0() {
    asm volatile("cp.async.wait_group 0;" ::: "memory");
}
__device__ __forceinline__ void cpwait1() {
    asm volatile("cp.async.wait_group 1;" ::: "memory");
}

// ---------------- tf32 mma.sync GEMM (unchanged from R4) --------------------
#define BK  32
#define SA  36
#define STG (128 * SA)
#define CHUNKS (D_MODEL / BK)
#define GEMM_SMEM (4 * STG * 4)

template <int HEAD_SPLIT>
__global__ void __launch_bounds__(256)
gemm_mma(const float* __restrict__ X, const float* __restrict__ W,
         const float* __restrict__ bias, float* __restrict__ out)
{
    extern __shared__ float smx[];
    float* As = smx;
    float* Bs = smx + 2 * STG;

    const int t    = threadIdx.x;
    const int wid  = t >> 5;
    const int lane = t & 31;
    const int g    = lane >> 2;
    const int tig  = lane & 3;
    const int wm   = (wid >> 1) * 32;
    const int wn   = (wid & 1) * 64;
    const int m0   = blockIdx.y * 128;
    const int n0   = blockIdx.x * 128;

    const int srow = t >> 1;
    const int scol = (t & 1) * 16;
    const float* Xp = X + (size_t)(m0 + srow) * D_MODEL + scol;
    const float* Wp = W + (size_t)(n0 + srow) * D_MODEL + scol;

    float4 ra[4], rb[4];
    float acc[2][8][4];
#pragma unroll
    for (int i = 0; i < 2; i++)
#pragma unroll
        for (int j = 0; j < 8; j++)
#pragma unroll
            for (int q = 0; q < 4; q++) acc[i][j][q] = 0.f;

#define LDREG(c) {                                                     \
        const int k0 = (c) * BK;                                       \
        _Pragma("unroll")                                              \
        for (int q = 0; q < 4; q++) {                                  \
            ra[q] = *(const float4*)(Xp + k0 + 4 * q);                 \
            rb[q] = *(const float4*)(Wp + k0 + 4 * q);                 \
        }                                                              \
    }
#define STSMEM(s) {                                                    \
        float* ap = As + (s) * STG + srow * SA + scol;                 \
        float* bp = Bs + (s) * STG + srow * SA + scol;                 \
        _Pragma("unroll")                                              \
        for (int q = 0; q < 4; q++) {                                  \
            float4 va = ra[q], vb = rb[q];                             \
            va.x = to_tf32(va.x); va.y = to_tf32(va.y);                \
            va.z = to_tf32(va.z); va.w = to_tf32(va.w);                \
            vb.x = to_tf32(vb.x); vb.y = to_tf32(vb.y);                \
            vb.z = to_tf32(vb.z); vb.w = to_tf32(vb.w);                \
            *(float4*)(ap + 4 * q) = va;                               \
            *(float4*)(bp + 4 * q) = vb;                               \
        }                                                              \
    }

    LDREG(0);
    STSMEM(0);
    __syncthreads();

    for (int c = 0; c < CHUNKS; c++) {
        const int s = c & 1;
        if (c + 1 < CHUNKS) LDREG(c + 1);

        const float* Af = As + s * STG;
        const float* Bf = Bs + s * STG;
#pragma unroll
        for (int ks = 0; ks < 4; ks++) {
            const int k = ks * 8;
            uint32_t afr[2][4];
#pragma unroll
            for (int i = 0; i < 2; i++) {
                const float* ap = Af + (wm + i * 16 + g) * SA + k + tig;
                afr[i][0] = __float_as_uint(ap[0]);
                afr[i][1] = __float_as_uint(ap[8 * SA]);
                afr[i][2] = __float_as_uint(ap[4]);
                afr[i][3] = __float_as_uint(ap[8 * SA + 4]);
            }
#pragma unroll
            for (int j = 0; j < 8; j++) {
                const float* bp = Bf + (wn + j * 8 + g) * SA + k + tig;
                uint32_t bfr[2] = { __float_as_uint(bp[0]), __float_as_uint(bp[4]) };
                mma8(acc[0][j], afr[0], bfr);
                mma8(acc[1][j], afr[1], bfr);
            }
        }

        if (c + 1 < CHUNKS) {
            __syncthreads();
            STSMEM((c + 1) & 1);
            __syncthreads();
        }
    }

#pragma unroll
    for (int i = 0; i < 2; i++) {
        const int r0 = m0 + wm + i * 16 + g;
#pragma unroll
        for (int j = 0; j < 8; j++) {
            const int n = n0 + wn + j * 8 + tig * 2;
            const float bx = bias[n], by = bias[n + 1];
            float2 lo = { acc[i][j][0] + bx, acc[i][j][1] + by };
            float2 hi = { acc[i][j][2] + bx, acc[i][j][3] + by };
            if (HEAD_SPLIT) {
                const int h = n >> 6, dk = n & 63;
                const int b0r = r0 >> 11, s0r = r0 & (S_ - 1);
                *(float2*)(out + (((size_t)(b0r * N_HEADS + h) * S_) + s0r) * D_KH + dk) = lo;
                const int r1 = r0 + 8;
                const int b1r = r1 >> 11, s1r = r1 & (S_ - 1);
                *(float2*)(out + (((size_t)(b1r * N_HEADS + h) * S_) + s1r) * D_KH + dk) = hi;
            } else {
                *(float2*)(out + (size_t)r0 * D_MODEL + n) = lo;
                *(float2*)(out + (size_t)(r0 + 8) * D_MODEL + n) = hi;
            }
        }
    }
}

// ---------------- tf32 mma.sync causal flash attention (v2) ----------------
// 128 q-rows per CTA, 256 threads = 8 warps x 16 rows. Q fragments in regs.
// K/V double-buffered via cp.async (overlap global with compute). K/V enter
// mma as raw fp32 (HW tf32 truncation); P explicitly RNA-rounded.
#define KST 68
#define VST 72
#define KTILE 64
#define ATTN_SMEM ((2 * 64 * KST + 2 * 64 * VST + 128 * KST) * 4)   // 106496 B

__global__ void __launch_bounds__(256, 2)
attn_mma(const float* __restrict__ gq, const float* __restrict__ gk,
         const float* __restrict__ gv, float* __restrict__ gout)
{
    extern __shared__ float sm[];
    float* Ks = sm;                              // [2][64][KST]
    float* Vs = sm + 2 * 64 * KST;               // [2][64][VST]
    float* Ps = sm + 2 * 64 * KST + 2 * 64 * VST; // [128][KST]

    const int qt = (S_ / 128 - 1) - blockIdx.x;  // heavy CTAs first
    const int h = blockIdx.y, b = blockIdx.z;
    const int tid  = threadIdx.x;
    const int w    = tid >> 5;
    const int lane = tid & 31;
    const int g    = lane >> 2;
    const int tig  = lane & 3;

    const size_t head = (size_t)(b * N_HEADS + h) * S_ * D_KH;
    const float* Qb = gq + head + (size_t)qt * 128 * D_KH;
    const float* Kb = gk + head;
    const float* Vb = gv + head;

    // cp.async staging: 256 threads cover a 64x64 tile; 4 x 16B each per op
    const int srK = tid >> 2;
    const int scK = (tid & 3) * 16;
    const uint32_t kdb = s2u(Ks) + (srK * KST + scK) * 4;
    const uint32_t vdb = s2u(Vs) + (srK * VST + scK) * 4;

#define STAGE_KV(kt, buf) {                                                   \
        const float* kp_ = Kb + (size_t)((kt) * KTILE + srK) * D_KH + scK;    \
        const float* vp_ = Vb + (size_t)((kt) * KTILE + srK) * D_KH + scK;    \
        const uint32_t kd_ = kdb + (buf) * (64 * KST * 4);                    \
        const uint32_t vd_ = vdb + (buf) * (64 * VST * 4);                    \
        _Pragma("unroll")                                                     \
        for (int q_ = 0; q_ < 4; q_++) {                                      \
            cpasync16(kd_ + 16 * q_, kp_ + 4 * q_);                           \
            cpasync16(vd_ + 16 * q_, vp_ + 4 * q_);                           \
        }                                                                     \
        cpcommit();                                                           \
    }

    STAGE_KV(0, 0);

    // stage Q (scaled 1/8, RNA tf32) into Ps
    {
        const int srow = tid >> 1;
        const int scol = (tid & 1) * 32;
        const float* qp = Qb + (size_t)srow * D_KH + scol;
        float* dp = Ps + srow * KST + scol;
#pragma unroll
        for (int q4 = 0; q4 < 8; q4++) {
            float4 v = *(const float4*)(qp + 4 * q4);
            v.x = to_tf32(v.x * 0.125f); v.y = to_tf32(v.y * 0.125f);
            v.z = to_tf32(v.z * 0.125f); v.w = to_tf32(v.w * 0.125f);
            *(float4*)(dp + 4 * q4) = v;
        }
    }
    __syncthreads();

    uint32_t aQ[8][4];
    {
        const float* Qw = Ps + (w * 16) * KST;
#pragma unroll
        for (int ks = 0; ks < 8; ks++) {
            aQ[ks][0] = __float_as_uint(Qw[g * KST + ks * 8 + tig]);
            aQ[ks][1] = __float_as_uint(Qw[(g + 8) * KST + ks * 8 + tig]);
            aQ[ks][2] = __float_as_uint(Qw[g * KST + ks * 8 + tig + 4]);
            aQ[ks][3] = __float_as_uint(Qw[(g + 8) * KST + ks * 8 + tig + 4]);
        }
    }

    float m0 = -1e30f, m1 = -1e30f, l0 = 0.f, l1 = 0.f;
    float of[8][4];
#pragma unroll
    for (int na = 0; na < 8; na++)
#pragma unroll
        for (int q = 0; q < 4; q++) of[na][q] = 0.f;

    const unsigned FULL = 0xffffffffu;
    const int rwarp = qt * 128 + w * 16;     // warp's first global row
    const int grow0 = rwarp + g;             // thread's rows: grow0, grow0+8
    const int ktmax = 2 * qt + 1;

    for (int kt = 0; kt <= ktmax; kt++) {
        if (kt < ktmax) STAGE_KV(kt + 1, (kt + 1) & 1);
        if (kt < ktmax) cpwait1(); else cpwait0();
        __syncthreads();

        const bool haswork = (kt * KTILE <= rwarp + 15);
        if (haswork) {
            const float* Kf = Ks + (kt & 1) * (64 * KST);
            const float* Vf = Vs + (kt & 1) * (64 * VST);

            // S = Q K^T
            float sf[8][4];
#pragma unroll
            for (int na = 0; na < 8; na++)
#pragma unroll
                for (int q = 0; q < 4; q++) sf[na][q] = 0.f;
#pragma unroll
            for (int na = 0; na < 8; na++) {
                const float* kp = Kf + (na * 8 + g) * KST + tig;
#pragma unroll
                for (int ks = 0; ks < 8; ks++) {
                    uint32_t bb[2] = { __float_as_uint(kp[ks * 8]),
                                       __float_as_uint(kp[ks * 8 + 4]) };
                    mma8(sf[na], aQ[ks], bb);
                }
            }

            if (kt * KTILE + 63 > rwarp) {   // diagonal: mask
#pragma unroll
                for (int na = 0; na < 8; na++) {
                    const int c0 = kt * KTILE + na * 8 + 2 * tig;
                    if (c0 > grow0)         sf[na][0] = -1e30f;
                    if (c0 + 1 > grow0)     sf[na][1] = -1e30f;
                    if (c0 > grow0 + 8)     sf[na][2] = -1e30f;
                    if (c0 + 1 > grow0 + 8) sf[na][3] = -1e30f;
                }
            }

            // fragment online softmax
            float mx0 = -1e30f, mx1 = -1e30f;
#pragma unroll
            for (int na = 0; na < 8; na++) {
                mx0 = fmaxf(mx0, fmaxf(sf[na][0], sf[na][1]));
                mx1 = fmaxf(mx1, fmaxf(sf[na][2], sf[na][3]));
            }
            mx0 = fmaxf(mx0, __shfl_xor_sync(FULL, mx0, 1));
            mx0 = fmaxf(mx0, __shfl_xor_sync(FULL, mx0, 2));
            mx1 = fmaxf(mx1, __shfl_xor_sync(FULL, mx1, 1));
            mx1 = fmaxf(mx1, __shfl_xor_sync(FULL, mx1, 2));
            const float mn0 = fmaxf(m0, mx0), mn1 = fmaxf(m1, mx1);
            const float a0 = __expf(m0 - mn0), a1 = __expf(m1 - mn1);

            float rs0 = 0.f, rs1 = 0.f;
            float* prow0 = Ps + (w * 16 + g) * KST;
            float* prow1 = prow0 + 8 * KST;
#pragma unroll
            for (int na = 0; na < 8; na++) {
                const float p00 = to_tf32(__expf(sf[na][0] - mn0));
                const float p01 = to_tf32(__expf(sf[na][1] - mn0));
                const float p10 = to_tf32(__expf(sf[na][2] - mn1));
                const float p11 = to_tf32(__expf(sf[na][3] - mn1));
                *(float2*)(prow0 + na * 8 + 2 * tig) = make_float2(p00, p01);
                *(float2*)(prow1 + na * 8 + 2 * tig) = make_float2(p10, p11);
                rs0 += p00 + p01; rs1 += p10 + p11;
                of[na][0] *= a0; of[na][1] *= a0;
                of[na][2] *= a1; of[na][3] *= a1;
            }
            rs0 += __shfl_xor_sync(FULL, rs0, 1);
            rs0 += __shfl_xor_sync(FULL, rs0, 2);
            rs1 += __shfl_xor_sync(FULL, rs1, 1);
            rs1 += __shfl_xor_sync(FULL, rs1, 2);
            l0 = l0 * a0 + rs0; m0 = mn0;
            l1 = l1 * a1 + rs1; m1 = mn1;
            __syncwarp();

            // O += P V
#pragma unroll
            for (int ks = 0; ks < 8; ks++) {
                const float* pr0 = Ps + (w * 16 + g) * KST + ks * 8 + tig;
                const float* pr1 = pr0 + 8 * KST;
                uint32_t pa[4] = { __float_as_uint(pr0[0]), __float_as_uint(pr1[0]),
                                   __float_as_uint(pr0[4]), __float_as_uint(pr1[4]) };
                const float* vp = Vf + (ks * 8 + tig) * VST + g;
#pragma unroll
                for (int na = 0; na < 8; na++) {
                    uint32_t bb[2] = { __float_as_uint(vp[na * 8]),
                                       __float_as_uint(vp[na * 8 + 4 * VST]) };
                    mma8(of[na], pa, bb);
                }
            }
            __syncwarp();
        }
        __syncthreads();
    }

    // epilogue: write [B,S,D]
    const float i0 = 1.f / l0, i1 = 1.f / l1;
    float* o0 = gout + ((size_t)(b * S_) + grow0) * D_MODEL + h * D_KH;
    float* o1 = o0 + (size_t)8 * D_MODEL;
#pragma unroll
    for (int na = 0; na < 8; na++) {
        *(float2*)(o0 + na * 8 + 2 * tig) = make_float2(of[na][0] * i0, of[na][1] * i0);
        *(float2*)(o1 + na * 8 + 2 * tig) = make_float2(of[na][2] * i1, of[na][3] * i1);
    }
}

// ---------------- host ------------------------------------------------------
extern "C" void kernel_launch(void* const* d_in, const int* in_sizes, int n_in,
                              void* d_out, int out_size)
{
    const float* Q   = (const float*)d_in[0];
    const float* K   = (const float*)d_in[1];
    const float* V   = (const float*)d_in[2];
    const float* W_q = (const float*)d_in[4];
    const float* b_q = (const float*)d_in[5];
    const float* W_k = (const float*)d_in[6];
    const float* b_k = (const float*)d_in[7];
    const float* W_v = (const float*)d_in[8];
    const float* b_v = (const float*)d_in[9];
    const float* W_o = (const float*)d_in[10];
    const float* b_o = (const float*)d_in[11];
    float* out = (float*)d_out;

    float *gq, *gk, *gv, *gattn;
    cudaGetSymbolAddress((void**)&gq, g_q);
    cudaGetSymbolAddress((void**)&gk, g_k);
    cudaGetSymbolAddress((void**)&gv, g_v);
    cudaGetSymbolAddress((void**)&gattn, g_attn);

    cudaFuncSetAttribute(gemm_mma<0>, cudaFuncAttributeMaxDynamicSharedMemorySize, GEMM_SMEM);
    cudaFuncSetAttribute(gemm_mma<1>, cudaFuncAttributeMaxDynamicSharedMemorySize, GEMM_SMEM);
    cudaFuncSetAttribute(attn_mma, cudaFuncAttributeMaxDynamicSharedMemorySize, ATTN_SMEM);

    dim3 ggrid(D_MODEL / 128, M_TOT / 128);   // (8, 64)
    gemm_mma<1><<<ggrid, 256, GEMM_SMEM>>>(Q, W_q, b_q, gq);
    gemm_mma<1><<<ggrid, 256, GEMM_SMEM>>>(K, W_k, b_k, gk);
    gemm_mma<1><<<ggrid, 256, GEMM_SMEM>>>(V, W_v, b_v, gv);

    attn_mma<<<dim3(S_ / 128, N_HEADS, B_), 256, ATTN_SMEM>>>(gq, gk, gv, gattn);

    gemm_mma<0><<<ggrid, 256, GEMM_SMEM>>>(gattn, W_o, b_o, out);
}